// round 14
// baseline (speedup 1.0000x reference)
#include <cuda_runtime.h>
#include <cuda_fp16.h>
#include <math.h>
#include <stdint.h>

#define M_ROWS 32768
#define H_DIM  1024
#define O_DIM  929
#define EPS_G  1e-20f

// ---------------------------------------------------------------------------
// Scratch (static device globals; no allocation allowed)
// ---------------------------------------------------------------------------
__device__ __align__(16) __half g_x16[(size_t)M_ROWS * 128];
__device__ __align__(16) __half g_h1[(size_t)M_ROWS * H_DIM];
__device__ __align__(16) __half g_h2[(size_t)M_ROWS * H_DIM];
__device__ __align__(16) __half g_w1t[1024 * 128];
__device__ __align__(16) __half g_w2t[1024 * 1024];
__device__ __align__(16) __half g_w3t[1024 * 1024];

// ---------------------------------------------------------------------------
// PTX helpers (sm_80-era, target-portable)
// ---------------------------------------------------------------------------
static __device__ __forceinline__ uint32_t smem_to_u32(const void* p) {
    uint32_t a;
    asm("{ .reg .u64 t; cvta.to.shared.u64 t, %1; cvt.u32.u64 %0, t; }"
        : "=r"(a) : "l"(p));
    return a;
}

#define CP_ASYNC16(dst, src) \
    asm volatile("cp.async.cg.shared.global [%0], [%1], 16;" :: "r"(dst), "l"(src))
#define CP_COMMIT() asm volatile("cp.async.commit_group;")
#define CP_WAIT1()  asm volatile("cp.async.wait_group 1;")
#define CP_WAIT0()  asm volatile("cp.async.wait_group 0;")

#define LDMX4(r, a) \
    asm volatile("ldmatrix.sync.aligned.m8n8.x4.shared.b16 {%0,%1,%2,%3}, [%4];" \
        : "=r"((r)[0]), "=r"((r)[1]), "=r"((r)[2]), "=r"((r)[3]) : "r"(a))

static __device__ __forceinline__ void mma16816(float* c, const uint32_t* a,
                                                uint32_t b0, uint32_t b1) {
    asm volatile(
        "mma.sync.aligned.m16n8k16.row.col.f32.f16.f16.f32 "
        "{%0,%1,%2,%3}, {%4,%5,%6,%7}, {%8,%9}, {%0,%1,%2,%3};"
        : "+f"(c[0]), "+f"(c[1]), "+f"(c[2]), "+f"(c[3])
        : "r"(a[0]), "r"(a[1]), "r"(a[2]), "r"(a[3]), "r"(b0), "r"(b1));
}

#define SWZ(o) ((o) ^ ((((uint32_t)(o)) >> 3) & 0x70))

// ---------------------------------------------------------------------------
// x convert: fp32 -> fp16
// ---------------------------------------------------------------------------
__global__ void convert_x_kernel(const float* __restrict__ x,
                                 __half* __restrict__ x16, int n)
{
    const int i = blockIdx.x * blockDim.x + threadIdx.x;
    if (i < n) x16[i] = __float2half(x[i]);
}

// ---------------------------------------------------------------------------
// Weight transpose: W [K,N] fp32 -> T [Npad,K] fp16 (rows >= N zero-filled)
// ---------------------------------------------------------------------------
__global__ void transpose_h_kernel(const float* __restrict__ W, int K, int N,
                                   __half* __restrict__ T)
{
    __shared__ float t[32][33];
    const int n0 = blockIdx.x * 32, k0 = blockIdx.y * 32;
    const int tx = threadIdx.x, ty = threadIdx.y;
#pragma unroll
    for (int j = 0; j < 32; j += 8) {
        const int k = k0 + ty + j, n = n0 + tx;
        t[ty + j][tx] = (n < N) ? W[(size_t)k * N + n] : 0.f;
    }
    __syncthreads();
#pragma unroll
    for (int j = 0; j < 32; j += 8) {
        const int n = n0 + ty + j, k = k0 + tx;
        T[(size_t)n * K + k] = __float2half(t[tx][ty + j]);
    }
}

// ---------------------------------------------------------------------------
// fp16 HMMA GEMM: C[M,Nlog] = act(A @ Bt^T + bias)
//   A  : fp16 [M,TK] row-major (K contig)
//   Bt : fp16 [Npad,TK] (K contig), Npad = gridDim.x*128
// BM=BN=128, BK=64, 256 threads, 8 warps (4m x 2n), warp tile 32x64.
// Triple-buffered cp.async, ONE barrier per stage; next-stage cp.asyncs are
// interleaved into the kk-loop (2 chunks per kk) to spread LSU pressure.
// TK compile-time: stage loop fully unrolled.
// __launch_bounds__(256, 2): 2 CTAs/SM (2 x 96 KB smem; 128-reg cap).
// ACT: 0 none, 1 ELU, 2 sigmoid.  HALF_OUT: write fp16, else fp32.
// ---------------------------------------------------------------------------
#define STAGE_BYTES 32768
#define GEMM_SMEM_BYTES (3 * STAGE_BYTES)

template <int TK, int ACT, bool HALF_OUT>
__global__ __launch_bounds__(256, 2)
void gemm_mma(const __half* __restrict__ A,
              const __half* __restrict__ B,
              const float* __restrict__ bias,
              float* __restrict__ Cf,
              __half* __restrict__ Ch,
              int Nlog)
{
    constexpr int NST = TK >> 6;
    extern __shared__ char smem[];
    const uint32_t sm0 = smem_to_u32(smem);

    const int tid = threadIdx.x, wid = tid >> 5, lane = tid & 31;
    const int m0 = blockIdx.y * 128, n0 = blockIdx.x * 128;
    const int wm = (wid & 3) * 32;     // warp m offset in tile
    const int wn = (wid >> 2) * 64;    // warp n offset in tile

    const __half* gA = A + (size_t)m0 * TK;
    const __half* gB = B + (size_t)n0 * TK;

    // 1024 16B chunks per operand part; thread t covers ci = 4t..4t+3
    const int ci0   = tid << 2;
    const int ldrow = ci0 >> 3;          // same row for all 4 chunks (8 chunks/row)
    const int ldch0 = ci0 & 7;

    // full-stage load (prologue only)
    auto load_stage = [&](int s, int buf) {
        const int k0 = s << 6;
        const uint32_t sb = sm0 + buf * STAGE_BYTES;
#pragma unroll
        for (int j = 0; j < 4; j++) {
            const uint32_t dst = SWZ((uint32_t)(ldrow * 128 + (ldch0 + j) * 16));
            const size_t   go  = (size_t)ldrow * TK + k0 + (ldch0 + j) * 8;
            CP_ASYNC16(sb + dst,         gA + go);
            CP_ASYNC16(sb + 16384 + dst, gB + go);
        }
        CP_COMMIT();
    };

    float c[16][4];
#pragma unroll
    for (int i = 0; i < 16; i++)
#pragma unroll
        for (int j = 0; j < 4; j++) c[i][j] = 0.f;

    // prologue: stages 0 and 1 in flight
    load_stage(0, 0);
    if (NST > 1) load_stage(1, 1);

    const int lrow = lane & 15;          // ldmatrix row within 16-row group
    const int lch  = (lane >> 4) << 4;   // 0 or 16 bytes (k sub-chunk)

#pragma unroll
    for (int s = 0; s < NST; s++) {
        const int buf = s % 3;
        // stage s must be complete:
        if (s + 1 < NST) { CP_WAIT1(); }
        else             { CP_WAIT0(); }
        __syncthreads();   // ALSO releases buffer (s+2)%3 for reuse

        const bool pre = (s + 2 < NST);
        const int  nbuf = (s + 2) % 3;
        const uint32_t psb = sm0 + nbuf * STAGE_BYTES;
        const int      pk0 = (s + 2) << 6;

        const uint32_t sb = sm0 + buf * STAGE_BYTES;
#pragma unroll
        for (int kk = 0; kk < 4; kk++) {
            // interleave: 1 chunk-pair of the (s+2) stage per kk iteration
            if (pre) {
                const uint32_t dst = SWZ((uint32_t)(ldrow * 128 + (ldch0 + kk) * 16));
                const size_t   go  = (size_t)ldrow * TK + pk0 + (ldch0 + kk) * 8;
                CP_ASYNC16(psb + dst,         gA + go);
                CP_ASYNC16(psb + 16384 + dst, gB + go);
            }

            uint32_t a[2][4], b[4][4];
#pragma unroll
            for (int am = 0; am < 2; am++) {
                const uint32_t o = SWZ((uint32_t)((wm + am * 16 + lrow) * 128 + kk * 32 + lch));
                LDMX4(a[am], sb + o);
            }
#pragma unroll
            for (int g = 0; g < 4; g++) {
                const uint32_t o = SWZ((uint32_t)((wn + g * 16 + lrow) * 128 + kk * 32 + lch));
                LDMX4(b[g], sb + 16384 + o);
            }
#pragma unroll
            for (int am = 0; am < 2; am++)
#pragma unroll
                for (int nb2 = 0; nb2 < 8; nb2++) {
                    const int g = nb2 >> 1, s2 = nb2 & 1;
                    mma16816(c[am * 8 + nb2], a[am], b[g][s2], b[g][s2 + 2]);
                }
        }
        if (pre) CP_COMMIT();
    }

    // epilogue: bias + activation
    const int g  = lane >> 2;
    const int tg = (lane & 3) << 1;
#pragma unroll
    for (int am = 0; am < 2; am++) {
        const int rbase = m0 + wm + am * 16 + g;
#pragma unroll
        for (int nb = 0; nb < 8; nb++) {
            const int col = n0 + wn + nb * 8 + tg;
            const float bi0 = __ldg(bias + col);
            const float bi1 = __ldg(bias + col + 1);
            float* cc = c[am * 8 + nb];
#pragma unroll
            for (int h = 0; h < 2; h++) {
                const int row = rbase + h * 8;
                float v0 = cc[h * 2 + 0] + bi0;
                float v1 = cc[h * 2 + 1] + bi1;
                if (ACT == 1) {
                    v0 = (v0 > 0.f) ? v0 : (__expf(v0) - 1.f);
                    v1 = (v1 > 0.f) ? v1 : (__expf(v1) - 1.f);
                } else if (ACT == 2) {
                    v0 = 1.f / (1.f + __expf(-v0));
                    v1 = 1.f / (1.f + __expf(-v1));
                }
                if (HALF_OUT) {
                    const size_t off = (size_t)row * Nlog + col;
                    *(__half2*)(Ch + off) = __floats2half2_rn(v0, v1);
                } else {
                    const size_t off = (size_t)row * Nlog + col;
                    if (col < Nlog)     Cf[off]     = v0;
                    if (col + 1 < Nlog) Cf[off + 1] = v1;
                }
            }
        }
    }
}

// ---------------------------------------------------------------------------
// Gumbel helper: g = -log(-log(u + eps) + eps)
// Inner log: MUFU fast path unless u > 0.99 (where |ln u| -> 0 makes MUFU's
// absolute error blow up relatively); outer log: always MUFU (abs err ~1.6e-7).
// ---------------------------------------------------------------------------
static __device__ __forceinline__ float gumbel_g(float u)
{
    const float up = u + EPS_G;
    float t;
    if (up <= 0.99f) t = -__logf(up);
    else             t = -logf(up);
    return -__logf(t + EPS_G);
}

// ---------------------------------------------------------------------------
// Gumbel softmax: one 288-thread block (9 warps) per row.
// Big segment (off=205, n=711): block-cooperative (2 block reductions).
// 9 small segments: one warp each, shfl-only reductions.
// ---------------------------------------------------------------------------
__constant__ int c_soff[9] = {0, 29, 32, 38, 45, 105, 129, 916, 919};
__constant__ int c_snum[9] = {29, 2, 6, 7, 59, 24, 76, 3, 9};

__global__ __launch_bounds__(288)
void gumbel_softmax2(float* __restrict__ out, const float* __restrict__ u)
{
    const int row = blockIdx.x, tid = threadIdx.x, wid = tid >> 5, lane = tid & 31;
    float* orow = out + (size_t)row * O_DIM;
    const float* urow = u + (size_t)row * O_DIM;
    __shared__ float red[16];
    __shared__ float bval;

    // ---- big segment: off=205, n=711 ----
    float y[3];
    float lmax = -3.4e38f;
#pragma unroll
    for (int it = 0; it < 3; it++) {
        const int i = tid + it * 288;
        if (i < 711) {
            const float v = (orow[205 + i] + gumbel_g(urow[205 + i])) * 1.25f;
            y[it] = v;
            lmax = fmaxf(lmax, v);
        } else y[it] = -3.4e38f;
    }
#pragma unroll
    for (int o = 16; o > 0; o >>= 1) lmax = fmaxf(lmax, __shfl_xor_sync(~0u, lmax, o));
    if (lane == 0) red[wid] = lmax;
    __syncthreads();
    if (tid < 32) {
        float w = (lane < 9) ? red[lane] : -3.4e38f;
#pragma unroll
        for (int o = 8; o > 0; o >>= 1) w = fmaxf(w, __shfl_xor_sync(~0u, w, o));
        if (lane == 0) bval = w;
    }
    __syncthreads();
    const float m = bval;
    float lsum = 0.f;
#pragma unroll
    for (int it = 0; it < 3; it++) {
        const int i = tid + it * 288;
        if (i < 711) { const float e = __expf(y[it] - m); y[it] = e; lsum += e; }
    }
#pragma unroll
    for (int o = 16; o > 0; o >>= 1) lsum += __shfl_xor_sync(~0u, lsum, o);
    if (lane == 0) red[wid] = lsum;
    __syncthreads();
    if (tid < 32) {
        float w = (lane < 9) ? red[lane] : 0.f;
#pragma unroll
        for (int o = 8; o > 0; o >>= 1) w += __shfl_xor_sync(~0u, w, o);
        if (lane == 0) bval = w;
    }
    __syncthreads();
    const float inv = 1.f / bval;
#pragma unroll
    for (int it = 0; it < 3; it++) {
        const int i = tid + it * 288;
        if (i < 711) orow[205 + i] = y[it] * inv;
    }

    // ---- small segments: warp `wid` handles segment `wid` ----
    {
        const int off = c_soff[wid], n = c_snum[wid];
        float z[3];
        float wmax = -3.4e38f;
#pragma unroll
        for (int it = 0; it < 3; it++) {
            const int i = lane + it * 32;
            if (i < n) {
                const float v = (orow[off + i] + gumbel_g(urow[off + i])) * 1.25f;
                z[it] = v;
                wmax = fmaxf(wmax, v);
            } else z[it] = -3.4e38f;
        }
#pragma unroll
        for (int o = 16; o > 0; o >>= 1) wmax = fmaxf(wmax, __shfl_xor_sync(~0u, wmax, o));
        float wsum = 0.f;
#pragma unroll
        for (int it = 0; it < 3; it++) {
            const int i = lane + it * 32;
            if (i < n) { const float e = __expf(z[it] - wmax); z[it] = e; wsum += e; }
        }
#pragma unroll
        for (int o = 16; o > 0; o >>= 1) wsum += __shfl_xor_sync(~0u, wsum, o);
        const float winv = 1.f / wsum;
#pragma unroll
        for (int it = 0; it < 3; it++) {
            const int i = lane + it * 32;
            if (i < n) orow[off + i] = z[it] * winv;
        }
    }
}

// ---------------------------------------------------------------------------
// Launch
// ---------------------------------------------------------------------------
extern "C" void kernel_launch(void* const* d_in, const int* in_sizes, int n_in,
                              void* d_out, int out_size)
{
    const float* x  = (const float*)d_in[0];
    const float* W1 = (const float*)d_in[1];
    const float* b1 = (const float*)d_in[2];
    const float* W2 = (const float*)d_in[3];
    const float* b2 = (const float*)d_in[4];
    const float* W3 = (const float*)d_in[5];
    const float* b3 = (const float*)d_in[6];
    const float* u  = (const float*)d_in[7];
    float* out = (float*)d_out;

    __half *x16, *h1, *h2, *w1t, *w2t, *w3t;
    cudaGetSymbolAddress((void**)&x16, g_x16);
    cudaGetSymbolAddress((void**)&h1,  g_h1);
    cudaGetSymbolAddress((void**)&h2,  g_h2);
    cudaGetSymbolAddress((void**)&w1t, g_w1t);
    cudaGetSymbolAddress((void**)&w2t, g_w2t);
    cudaGetSymbolAddress((void**)&w3t, g_w3t);

    cudaFuncSetAttribute(gemm_mma<128,  1, true>,  cudaFuncAttributeMaxDynamicSharedMemorySize, GEMM_SMEM_BYTES);
    cudaFuncSetAttribute(gemm_mma<1024, 2, true>,  cudaFuncAttributeMaxDynamicSharedMemorySize, GEMM_SMEM_BYTES);
    cudaFuncSetAttribute(gemm_mma<1024, 0, false>, cudaFuncAttributeMaxDynamicSharedMemorySize, GEMM_SMEM_BYTES);

    // input / weight preparation
    convert_x_kernel<<<(M_ROWS * 128 + 255) / 256, 256>>>(x, x16, M_ROWS * 128);
    dim3 tsb(32, 8);
    transpose_h_kernel<<<dim3(32, 4),  tsb>>>(W1, 128,  1024, w1t);
    transpose_h_kernel<<<dim3(32, 32), tsb>>>(W2, 1024, 1024, w2t);
    transpose_h_kernel<<<dim3(32, 32), tsb>>>(W3, 1024, 929,  w3t);

    dim3 grid(8, 256), block(256);
    // h1 = elu(x @ W1 + b1), fp16
    gemm_mma<128, 1, true><<<grid, block, GEMM_SMEM_BYTES>>>(
        x16, w1t, b1, nullptr, h1, H_DIM);
    // h2 = sigmoid(h1 @ W2 + b2), fp16
    gemm_mma<1024, 2, true><<<grid, block, GEMM_SMEM_BYTES>>>(
        h1, w2t, b2, nullptr, h2, H_DIM);
    // logits = h2 @ W3 + b3, fp32 to d_out
    gemm_mma<1024, 0, false><<<grid, block, GEMM_SMEM_BYTES>>>(
        h2, w3t, b3, out, nullptr, O_DIM);
    // segmented gumbel softmax in place
    gumbel_softmax2<<<M_ROWS, 288>>>(out, u);
}

// round 15
// speedup vs baseline: 1.4013x; 1.4013x over previous
#include <cuda_runtime.h>
#include <cuda_fp16.h>
#include <math.h>
#include <stdint.h>

#define M_ROWS 32768
#define H_DIM  1024
#define O_DIM  929
#define EPS_G  1e-20f

// ---------------------------------------------------------------------------
// Scratch (static device globals; no allocation allowed)
// ---------------------------------------------------------------------------
__device__ __align__(16) __half g_x16[(size_t)M_ROWS * 128];
__device__ __align__(16) __half g_h1[(size_t)M_ROWS * H_DIM];
__device__ __align__(16) __half g_h2[(size_t)M_ROWS * H_DIM];
__device__ __align__(16) __half g_w1t[1024 * 128];
__device__ __align__(16) __half g_w2t[1024 * 1024];
__device__ __align__(16) __half g_w3t[1024 * 1024];

// ---------------------------------------------------------------------------
// PTX helpers (sm_80-era, target-portable)
// ---------------------------------------------------------------------------
static __device__ __forceinline__ uint32_t smem_to_u32(const void* p) {
    uint32_t a;
    asm("{ .reg .u64 t; cvta.to.shared.u64 t, %1; cvt.u32.u64 %0, t; }"
        : "=r"(a) : "l"(p));
    return a;
}

#define CP_ASYNC16(dst, src) \
    asm volatile("cp.async.cg.shared.global [%0], [%1], 16;" :: "r"(dst), "l"(src))
#define CP_COMMIT() asm volatile("cp.async.commit_group;")
#define CP_WAIT1()  asm volatile("cp.async.wait_group 1;")
#define CP_WAIT0()  asm volatile("cp.async.wait_group 0;")

#define LDMX4(r, a) \
    asm volatile("ldmatrix.sync.aligned.m8n8.x4.shared.b16 {%0,%1,%2,%3}, [%4];" \
        : "=r"((r)[0]), "=r"((r)[1]), "=r"((r)[2]), "=r"((r)[3]) : "r"(a))

static __device__ __forceinline__ void mma16816(float* c, const uint32_t* a,
                                                uint32_t b0, uint32_t b1) {
    asm volatile(
        "mma.sync.aligned.m16n8k16.row.col.f32.f16.f16.f32 "
        "{%0,%1,%2,%3}, {%4,%5,%6,%7}, {%8,%9}, {%0,%1,%2,%3};"
        : "+f"(c[0]), "+f"(c[1]), "+f"(c[2]), "+f"(c[3])
        : "r"(a[0]), "r"(a[1]), "r"(a[2]), "r"(a[3]), "r"(b0), "r"(b1));
}

#define SWZ(o) ((o) ^ ((((uint32_t)(o)) >> 3) & 0x70))

// ---------------------------------------------------------------------------
// x convert: fp32 -> fp16
// ---------------------------------------------------------------------------
__global__ void convert_x_kernel(const float* __restrict__ x,
                                 __half* __restrict__ x16, int n)
{
    const int i = blockIdx.x * blockDim.x + threadIdx.x;
    if (i < n) x16[i] = __float2half(x[i]);
}

// ---------------------------------------------------------------------------
// Weight transpose: W [K,N] fp32 -> T [Npad,K] fp16 (rows >= N zero-filled)
// ---------------------------------------------------------------------------
__global__ void transpose_h_kernel(const float* __restrict__ W, int K, int N,
                                   __half* __restrict__ T)
{
    __shared__ float t[32][33];
    const int n0 = blockIdx.x * 32, k0 = blockIdx.y * 32;
    const int tx = threadIdx.x, ty = threadIdx.y;
#pragma unroll
    for (int j = 0; j < 32; j += 8) {
        const int k = k0 + ty + j, n = n0 + tx;
        t[ty + j][tx] = (n < N) ? W[(size_t)k * N + n] : 0.f;
    }
    __syncthreads();
#pragma unroll
    for (int j = 0; j < 32; j += 8) {
        const int n = n0 + ty + j, k = k0 + tx;
        T[(size_t)n * K + k] = __float2half(t[tx][ty + j]);
    }
}

// ---------------------------------------------------------------------------
// fp16 HMMA GEMM: C[M,Nlog] = act(A @ Bt^T + bias)
//   A  : fp16 [M,K] row-major (K contig)
//   Bt : fp16 [Npad,K] (K contig), Npad = gridDim.x*128
// BM=BN=128, BK=64, 256 threads, 8 warps (4m x 2n), warp tile 32x64.
// Triple-buffered cp.async, ONE barrier per stage; runtime stage loop
// (small body, stays L0-I$-resident). Next-stage cp.asyncs are interleaved
// into the kk-loop (2 of 8 per kk) to spread LSU pressure away from LDSM.
// __launch_bounds__(256, 2): 2 CTAs/SM (2 x 96 KB smem; 128-reg cap).
// ACT: 0 none, 1 ELU, 2 sigmoid.  HALF_OUT: write fp16, else fp32.
// ---------------------------------------------------------------------------
#define STAGE_BYTES 32768
#define GEMM_SMEM_BYTES (3 * STAGE_BYTES)

template <int ACT, bool HALF_OUT>
__global__ __launch_bounds__(256, 2)
void gemm_mma(const __half* __restrict__ A,
              const __half* __restrict__ B,
              const float* __restrict__ bias,
              float* __restrict__ Cf,
              __half* __restrict__ Ch,
              int Nlog, int K)
{
    extern __shared__ char smem[];
    const uint32_t sm0 = smem_to_u32(smem);

    const int tid = threadIdx.x, wid = tid >> 5, lane = tid & 31;
    const int m0 = blockIdx.y * 128, n0 = blockIdx.x * 128;
    const int wm = (wid & 3) * 32;     // warp m offset in tile
    const int wn = (wid >> 2) * 64;    // warp n offset in tile

    const __half* gA = A + (size_t)m0 * K;
    const __half* gB = B + (size_t)n0 * K;

    // 1024 16B chunks per operand part; thread t covers ci = 4t..4t+3
    const int ci0   = tid << 2;
    const int ldrow = ci0 >> 3;          // same row for all 4 chunks
    const int ldch0 = ci0 & 7;

    // full-stage load (prologue only)
    auto load_stage = [&](int s, int buf) {
        const int k0 = s << 6;
        const uint32_t sb = sm0 + buf * STAGE_BYTES;
#pragma unroll
        for (int j = 0; j < 4; j++) {
            const uint32_t dst = SWZ((uint32_t)(ldrow * 128 + (ldch0 + j) * 16));
            const size_t   go  = (size_t)ldrow * K + k0 + (ldch0 + j) * 8;
            CP_ASYNC16(sb + dst,         gA + go);
            CP_ASYNC16(sb + 16384 + dst, gB + go);
        }
        CP_COMMIT();
    };

    float c[16][4];
#pragma unroll
    for (int i = 0; i < 16; i++)
#pragma unroll
        for (int j = 0; j < 4; j++) c[i][j] = 0.f;

    const int nst = K >> 6;
    // prologue: stages 0 and 1 in flight
    load_stage(0, 0);
    if (nst > 1) load_stage(1, 1);

    const int lrow = lane & 15;          // ldmatrix row within 16-row group
    const int lch  = (lane >> 4) << 4;   // 0 or 16 bytes (k sub-chunk)

    int buf = 0;                          // buf = s % 3
    for (int s = 0; s < nst; s++) {
        // stage s must be complete:
        if (s + 1 < nst) { CP_WAIT1(); }
        else             { CP_WAIT0(); }
        __syncthreads();   // ALSO releases buffer (s+2)%3 for reuse

        const bool pre = (s + 2 < nst);
        int nbuf = buf + 2; if (nbuf >= 3) nbuf -= 3;
        const uint32_t psb = sm0 + nbuf * STAGE_BYTES;
        const int      pk0 = (s + 2) << 6;

        const uint32_t sb = sm0 + buf * STAGE_BYTES;
#pragma unroll
        for (int kk = 0; kk < 4; kk++) {
            // interleave: 1 chunk-pair of stage s+2 per kk iteration
            if (pre) {
                const uint32_t dst = SWZ((uint32_t)(ldrow * 128 + (ldch0 + kk) * 16));
                const size_t   go  = (size_t)ldrow * K + pk0 + (ldch0 + kk) * 8;
                CP_ASYNC16(psb + dst,         gA + go);
                CP_ASYNC16(psb + 16384 + dst, gB + go);
            }

            uint32_t a[2][4], b[4][4];
#pragma unroll
            for (int am = 0; am < 2; am++) {
                const uint32_t o = SWZ((uint32_t)((wm + am * 16 + lrow) * 128 + kk * 32 + lch));
                LDMX4(a[am], sb + o);
            }
#pragma unroll
            for (int g = 0; g < 4; g++) {
                const uint32_t o = SWZ((uint32_t)((wn + g * 16 + lrow) * 128 + kk * 32 + lch));
                LDMX4(b[g], sb + 16384 + o);
            }
#pragma unroll
            for (int am = 0; am < 2; am++)
#pragma unroll
                for (int nb2 = 0; nb2 < 8; nb2++) {
                    const int g = nb2 >> 1, s2 = nb2 & 1;
                    mma16816(c[am * 8 + nb2], a[am], b[g][s2], b[g][s2 + 2]);
                }
        }
        if (pre) CP_COMMIT();
        if (++buf == 3) buf = 0;
    }

    // epilogue: bias + activation
    const int g  = lane >> 2;
    const int tg = (lane & 3) << 1;
#pragma unroll
    for (int am = 0; am < 2; am++) {
        const int rbase = m0 + wm + am * 16 + g;
#pragma unroll
        for (int nb = 0; nb < 8; nb++) {
            const int col = n0 + wn + nb * 8 + tg;
            const float bi0 = __ldg(bias + col);
            const float bi1 = __ldg(bias + col + 1);
            float* cc = c[am * 8 + nb];
#pragma unroll
            for (int h = 0; h < 2; h++) {
                const int row = rbase + h * 8;
                float v0 = cc[h * 2 + 0] + bi0;
                float v1 = cc[h * 2 + 1] + bi1;
                if (ACT == 1) {
                    v0 = (v0 > 0.f) ? v0 : (__expf(v0) - 1.f);
                    v1 = (v1 > 0.f) ? v1 : (__expf(v1) - 1.f);
                } else if (ACT == 2) {
                    v0 = 1.f / (1.f + __expf(-v0));
                    v1 = 1.f / (1.f + __expf(-v1));
                }
                if (HALF_OUT) {
                    const size_t off = (size_t)row * Nlog + col;
                    *(__half2*)(Ch + off) = __floats2half2_rn(v0, v1);
                } else {
                    const size_t off = (size_t)row * Nlog + col;
                    if (col < Nlog)     Cf[off]     = v0;
                    if (col + 1 < Nlog) Cf[off + 1] = v1;
                }
            }
        }
    }
}

// ---------------------------------------------------------------------------
// Gumbel helper: g = -log(-log(u + eps) + eps)
// Inner log: MUFU fast path unless u > 0.99 (where |ln u| -> 0 makes MUFU's
// absolute error blow up relatively); outer log: always MUFU (abs err ~1.6e-7).
// ---------------------------------------------------------------------------
static __device__ __forceinline__ float gumbel_g(float u)
{
    const float up = u + EPS_G;
    float t;
    if (up <= 0.99f) t = -__logf(up);
    else             t = -logf(up);
    return -__logf(t + EPS_G);
}

// ---------------------------------------------------------------------------
// Gumbel softmax: one 288-thread block (9 warps) per row.
// Big segment (off=205, n=711): block-cooperative (2 block reductions).
// 9 small segments: one warp each, shfl-only reductions.
// ---------------------------------------------------------------------------
__constant__ int c_soff[9] = {0, 29, 32, 38, 45, 105, 129, 916, 919};
__constant__ int c_snum[9] = {29, 2, 6, 7, 59, 24, 76, 3, 9};

__global__ __launch_bounds__(288)
void gumbel_softmax2(float* __restrict__ out, const float* __restrict__ u)
{
    const int row = blockIdx.x, tid = threadIdx.x, wid = tid >> 5, lane = tid & 31;
    float* orow = out + (size_t)row * O_DIM;
    const float* urow = u + (size_t)row * O_DIM;
    __shared__ float red[16];
    __shared__ float bval;

    // ---- big segment: off=205, n=711 ----
    float y[3];
    float lmax = -3.4e38f;
#pragma unroll
    for (int it = 0; it < 3; it++) {
        const int i = tid + it * 288;
        if (i < 711) {
            const float v = (orow[205 + i] + gumbel_g(__ldg(urow + 205 + i))) * 1.25f;
            y[it] = v;
            lmax = fmaxf(lmax, v);
        } else y[it] = -3.4e38f;
    }
#pragma unroll
    for (int o = 16; o > 0; o >>= 1) lmax = fmaxf(lmax, __shfl_xor_sync(~0u, lmax, o));
    if (lane == 0) red[wid] = lmax;
    __syncthreads();
    if (tid < 32) {
        float w = (lane < 9) ? red[lane] : -3.4e38f;
#pragma unroll
        for (int o = 8; o > 0; o >>= 1) w = fmaxf(w, __shfl_xor_sync(~0u, w, o));
        if (lane == 0) bval = w;
    }
    __syncthreads();
    const float m = bval;
    float lsum = 0.f;
#pragma unroll
    for (int it = 0; it < 3; it++) {
        const int i = tid + it * 288;
        if (i < 711) { const float e = __expf(y[it] - m); y[it] = e; lsum += e; }
    }
#pragma unroll
    for (int o = 16; o > 0; o >>= 1) lsum += __shfl_xor_sync(~0u, lsum, o);
    if (lane == 0) red[wid] = lsum;
    __syncthreads();
    if (tid < 32) {
        float w = (lane < 9) ? red[lane] : 0.f;
#pragma unroll
        for (int o = 8; o > 0; o >>= 1) w += __shfl_xor_sync(~0u, w, o);
        if (lane == 0) bval = w;
    }
    __syncthreads();
    const float inv = 1.f / bval;
#pragma unroll
    for (int it = 0; it < 3; it++) {
        const int i = tid + it * 288;
        if (i < 711) orow[205 + i] = y[it] * inv;
    }

    // ---- small segments: warp `wid` handles segment `wid` ----
    {
        const int off = c_soff[wid], n = c_snum[wid];
        float z[3];
        float wmax = -3.4e38f;
#pragma unroll
        for (int it = 0; it < 3; it++) {
            const int i = lane + it * 32;
            if (i < n) {
                const float v = (orow[off + i] + gumbel_g(__ldg(urow + off + i))) * 1.25f;
                z[it] = v;
                wmax = fmaxf(wmax, v);
            } else z[it] = -3.4e38f;
        }
#pragma unroll
        for (int o = 16; o > 0; o >>= 1) wmax = fmaxf(wmax, __shfl_xor_sync(~0u, wmax, o));
        float wsum = 0.f;
#pragma unroll
        for (int it = 0; it < 3; it++) {
            const int i = lane + it * 32;
            if (i < n) { const float e = __expf(z[it] - wmax); z[it] = e; wsum += e; }
        }
#pragma unroll
        for (int o = 16; o > 0; o >>= 1) wsum += __shfl_xor_sync(~0u, wsum, o);
        const float winv = 1.f / wsum;
#pragma unroll
        for (int it = 0; it < 3; it++) {
            const int i = lane + it * 32;
            if (i < n) orow[off + i] = z[it] * winv;
        }
    }
}

// ---------------------------------------------------------------------------
// Launch
// ---------------------------------------------------------------------------
extern "C" void kernel_launch(void* const* d_in, const int* in_sizes, int n_in,
                              void* d_out, int out_size)
{
    const float* x  = (const float*)d_in[0];
    const float* W1 = (const float*)d_in[1];
    const float* b1 = (const float*)d_in[2];
    const float* W2 = (const float*)d_in[3];
    const float* b2 = (const float*)d_in[4];
    const float* W3 = (const float*)d_in[5];
    const float* b3 = (const float*)d_in[6];
    const float* u  = (const float*)d_in[7];
    float* out = (float*)d_out;

    __half *x16, *h1, *h2, *w1t, *w2t, *w3t;
    cudaGetSymbolAddress((void**)&x16, g_x16);
    cudaGetSymbolAddress((void**)&h1,  g_h1);
    cudaGetSymbolAddress((void**)&h2,  g_h2);
    cudaGetSymbolAddress((void**)&w1t, g_w1t);
    cudaGetSymbolAddress((void**)&w2t, g_w2t);
    cudaGetSymbolAddress((void**)&w3t, g_w3t);

    cudaFuncSetAttribute(gemm_mma<1, true>,  cudaFuncAttributeMaxDynamicSharedMemorySize, GEMM_SMEM_BYTES);
    cudaFuncSetAttribute(gemm_mma<2, true>,  cudaFuncAttributeMaxDynamicSharedMemorySize, GEMM_SMEM_BYTES);
    cudaFuncSetAttribute(gemm_mma<0, false>, cudaFuncAttributeMaxDynamicSharedMemorySize, GEMM_SMEM_BYTES);

    // input / weight preparation
    convert_x_kernel<<<(M_ROWS * 128 + 255) / 256, 256>>>(x, x16, M_ROWS * 128);
    dim3 tsb(32, 8);
    transpose_h_kernel<<<dim3(32, 4),  tsb>>>(W1, 128,  1024, w1t);
    transpose_h_kernel<<<dim3(32, 32), tsb>>>(W2, 1024, 1024, w2t);
    transpose_h_kernel<<<dim3(32, 32), tsb>>>(W3, 1024, 929,  w3t);

    dim3 grid(8, 256), block(256);
    // h1 = elu(x @ W1 + b1), fp16
    gemm_mma<1, true><<<grid, block, GEMM_SMEM_BYTES>>>(
        x16, w1t, b1, nullptr, h1, H_DIM, 128);
    // h2 = sigmoid(h1 @ W2 + b2), fp16
    gemm_mma<2, true><<<grid, block, GEMM_SMEM_BYTES>>>(
        h1, w2t, b2, nullptr, h2, H_DIM, H_DIM);
    // logits = h2 @ W3 + b3, fp32 to d_out
    gemm_mma<0, false><<<grid, block, GEMM_SMEM_BYTES>>>(
        h2, w3t, b3, out, nullptr, O_DIM, H_DIM);
    // segmented gumbel softmax in place
    gumbel_softmax2<<<M_ROWS, 288>>>(out, u);
}